// round 2
// baseline (speedup 1.0000x reference)
#include <cuda_runtime.h>
#include <math.h>

#define INFV 1e10f
#define NB    8
#define NSEQ  1024
#define NDIM  64
#define NPAIR 5
#define NPB   40               // pair*8 + batch
#define NDIAG 2047

// tensor order matches d_in: 0=TGT, 1=OTH, 2=X
__constant__ int c_pa[NPAIR] = {2, 0, 0, 1, 1};  // first arg (rows i)
__constant__ int c_pb[NPAIR] = {2, 2, 0, 2, 1};  // second arg (rows j)

// scratch (static device allocations are allowed)
__device__ float g_norm[3 * NB * NSEQ * NDIM];                 // ~6 MB
__device__ float g_diag[(size_t)NPB * NDIAG * NSEQ];           // ~335 MB, diag-major cost
__device__ float g_sdtw[NPB];

// ---------------------------------------------------------------------------
// Kernel 1: row-normalize all three tensors. One warp per row (D=64 -> float2/lane)
// ---------------------------------------------------------------------------
__global__ void norm_kernel(const float* __restrict__ TGT,
                            const float* __restrict__ OTH,
                            const float* __restrict__ X) {
    int row  = blockIdx.x * 8 + (threadIdx.x >> 5);   // 0 .. 24575
    int lane = threadIdx.x & 31;
    const float* src = (row < 8192) ? TGT : (row < 16384 ? OTH : X);
    int lrow = row & 8191;
    float2 v = reinterpret_cast<const float2*>(src + (size_t)lrow * NDIM)[lane];
    float s = v.x * v.x + v.y * v.y;
    #pragma unroll
    for (int o = 16; o; o >>= 1) s += __shfl_xor_sync(0xffffffffu, s, o);
    float scale = (s > 1e-16f) ? rsqrtf(s) : 1e8f;
    float2 out = make_float2(v.x * scale, v.y * scale);
    reinterpret_cast<float2*>(g_norm + (size_t)row * NDIM)[lane] = out;
}

// ---------------------------------------------------------------------------
// Kernel 2: cost = 1 - A_n . B_n^T per (pair,batch), written DIAGONAL-MAJOR.
// 128x128 output tile per CTA, K=64 in chunks of 16, 256 threads, 8x8 micro.
// Epilogue stages 32-row chunks in SMEM and emits contiguous diagonal runs.
// ---------------------------------------------------------------------------
__global__ void __launch_bounds__(256) cost_kernel() {
    const int pb    = blockIdx.y;           // 0..39
    const int pair  = pb >> 3;
    const int batch = pb & 7;
    const int ti    = blockIdx.x >> 3;
    const int tj    = blockIdx.x & 7;
    const int i0 = ti * 128, j0 = tj * 128;

    const float* Ap = g_norm + ((size_t)(c_pa[pair] * NB + batch)) * NSEQ * NDIM + (size_t)i0 * NDIM;
    const float* Bp = g_norm + ((size_t)(c_pb[pair] * NB + batch)) * NSEQ * NDIM + (size_t)j0 * NDIM;

    __shared__ float sbuf[4608];            // As[16][128] | Bs[16][128] ; reused as Cs[32][136]
    float* As = sbuf;
    float* Bs = sbuf + 2048;

    const int t  = threadIdx.x;
    const int tx = t & 15, ty = t >> 4;

    float acc[8][8];
    #pragma unroll
    for (int u = 0; u < 8; u++)
        #pragma unroll
        for (int v = 0; v < 8; v++) acc[u][v] = 0.f;

    for (int kc = 0; kc < NDIM; kc += 16) {
        __syncthreads();
        #pragma unroll
        for (int q = 0; q < 2; q++) {
            int id = t * 2 + q;             // 0..511
            int r  = id >> 2;               // row within tile
            int kq = id & 3;                // which float4 of the 16-wide K chunk
            float4 va = reinterpret_cast<const float4*>(Ap + r * NDIM + kc)[kq];
            As[(kq * 4 + 0) * 128 + r] = va.x;
            As[(kq * 4 + 1) * 128 + r] = va.y;
            As[(kq * 4 + 2) * 128 + r] = va.z;
            As[(kq * 4 + 3) * 128 + r] = va.w;
            float4 vb = reinterpret_cast<const float4*>(Bp + r * NDIM + kc)[kq];
            Bs[(kq * 4 + 0) * 128 + r] = vb.x;
            Bs[(kq * 4 + 1) * 128 + r] = vb.y;
            Bs[(kq * 4 + 2) * 128 + r] = vb.z;
            Bs[(kq * 4 + 3) * 128 + r] = vb.w;
        }
        __syncthreads();
        #pragma unroll
        for (int kk = 0; kk < 16; kk++) {
            float a[8], b[8];
            *(float4*)(a)     = *(float4*)&As[kk * 128 + ty * 8];
            *(float4*)(a + 4) = *(float4*)&As[kk * 128 + ty * 8 + 4];
            *(float4*)(b)     = *(float4*)&Bs[kk * 128 + tx * 8];
            *(float4*)(b + 4) = *(float4*)&Bs[kk * 128 + tx * 8 + 4];
            #pragma unroll
            for (int u = 0; u < 8; u++)
                #pragma unroll
                for (int v = 0; v < 8; v++) acc[u][v] += a[u] * b[v];
        }
    }

    // epilogue: 4 chunks of 32 rows, diag-major coalesced writes
    float* Cs = sbuf;                       // 32 x 136
    const size_t dbase = (size_t)pb * ((size_t)NDIAG * NSEQ);
    const int wid = t >> 5, lane = t & 31;
    for (int c = 0; c < 4; c++) {
        __syncthreads();
        if ((ty >> 2) == c) {
            int ri = (ty & 3) * 8;
            #pragma unroll
            for (int u = 0; u < 8; u++) {
                *(float4*)&Cs[(ri + u) * 136 + tx * 8]     = *(float4*)&acc[u][0];
                *(float4*)&Cs[(ri + u) * 136 + tx * 8 + 4] = *(float4*)&acc[u][4];
            }
        }
        __syncthreads();
        int kb  = i0 + j0 + c * 32;         // global k of local diag 0
        int gi0 = i0 + c * 32;
        for (int kl = wid; kl < 159; kl += 8) {
            int ri = lane;
            int jl = kl - ri;
            if (jl >= 0 && jl < 128 && ri < 32) {
                g_diag[dbase + (size_t)(kb + kl) * NSEQ + (gi0 + ri)] =
                    1.0f - Cs[ri * 136 + jl];
            }
        }
    }
}

// ---------------------------------------------------------------------------
// Kernel 3: soft-DTW DP over anti-diagonals. One CTA per (pair,batch),
// 1024 threads, thread i = row i.
//  - warp-activity window: fully-invalid warps skip everything but the barrier
//  - 3 MUFU per cell (min term contributes exp(0)=1 for free)
//  - single shfl per step: ul is last step's up, carried in a register
//  - cost prefetched 3 diagonals ahead
// ---------------------------------------------------------------------------
__global__ void __launch_bounds__(1024, 1) dp_kernel() {
    const int pb = blockIdx.x;
    const float* __restrict__ diag = g_diag + (size_t)pb * ((size_t)NDIAG * NSEQ);
    const int i    = threadIdx.x;
    const int w    = i >> 5;
    const int lane = i & 31;

    // boundary ring: bd[parity][w+1] written by warp w's lane31.
    // column 0 is a permanent INFV wall for warp 0 (no branch needed).
    __shared__ float bd[2][33];
    if (i < 66) ((float*)bd)[i] = INFV;
    __syncthreads();

    const int lo = max(0, w * 32 - 2);
    const int hi = min(NDIAG - 1, w * 32 + 31 + 1023 + 4);

    float d1 = INFV;                         // R[k-1], row i
    float ul = (i == 0) ? 0.0f : INFV;       // R[k-2], row i-1 (corner seed at k==0)
    float c0 = 0.f, c1 = 0.f, c2 = 0.f;

    for (int k = 0; k < NDIAG; k++) {
        if (k >= lo && k <= hi) {
            if (k == lo) {
                c0 = diag[(size_t)k * NSEQ + i];
                c1 = (k + 1 < NDIAG) ? diag[(size_t)(k + 1) * NSEQ + i] : 0.f;
                c2 = (k + 2 < NDIAG) ? diag[(size_t)(k + 2) * NSEQ + i] : 0.f;
            }
            float cnext = (k + 3 < NDIAG) ? diag[(size_t)(k + 3) * NSEQ + i] : 0.f;

            float up = __shfl_up_sync(0xffffffffu, d1, 1);   // R[k-1], row i-1
            if (lane == 0) up = bd[(k & 1) ^ 1][w];

            // exact 3-sort, then softmin with the min's exp term folded to 1
            float lo2 = fminf(ul, up);
            float hi2 = fmaxf(ul, up);
            float mn  = fminf(lo2, d1);
            float mx  = fmaxf(hi2, d1);
            float md  = fmaxf(lo2, fminf(hi2, d1));
            float s   = 1.0f + __expf(mn - md) + __expf(mn - mx);
            float smn = mn - __logf(s);

            int   j   = k - i;
            float cur = (j >= 0 && j < NSEQ) ? (c0 + smn) : INFV;

            d1 = cur;
            ul = up;
            if (lane == 31) bd[k & 1][w + 1] = d1;
            c0 = c1; c1 = c2; c2 = cnext;
        }
        __syncthreads();
    }

    if (i == NSEQ - 1) g_sdtw[pb] = d1;
}

// ---------------------------------------------------------------------------
// Kernel 4: final MSE reduction
// ---------------------------------------------------------------------------
__global__ void final_kernel(const float* __restrict__ labels, float* __restrict__ out) {
    int b = threadIdx.x;
    float v = 0.f;
    if (b < NB) {
        float sXX = g_sdtw[0 * NB + b];
        float sTX = g_sdtw[1 * NB + b];
        float sTT = g_sdtw[2 * NB + b];
        float sOX = g_sdtw[3 * NB + b];
        float sOO = g_sdtw[4 * NB + b];
        float dt = sTX - 0.5f * (sTT + sXX);
        float dq = sOX - 0.5f * (sOO + sXX);
        float e  = dt - dq - labels[0];
        v = e * e;
    }
    #pragma unroll
    for (int o = 16; o; o >>= 1) v += __shfl_xor_sync(0xffffffffu, v, o);
    if (b == 0) out[0] = v * (1.0f / NB);
}

// ---------------------------------------------------------------------------
extern "C" void kernel_launch(void* const* d_in, const int* in_sizes, int n_in,
                              void* d_out, int out_size) {
    const float* TGT    = (const float*)d_in[0];
    const float* OTH    = (const float*)d_in[1];
    const float* X      = (const float*)d_in[2];
    const float* labels = (const float*)d_in[3];
    float* out = (float*)d_out;

    norm_kernel<<<3072, 256>>>(TGT, OTH, X);
    cost_kernel<<<dim3(64, NPB), 256>>>();
    dp_kernel<<<NPB, 1024>>>();
    final_kernel<<<1, 32>>>(labels, out);
}

// round 4
// speedup vs baseline: 2.6392x; 2.6392x over previous
#include <cuda_runtime.h>
#include <math.h>

#define NB    8
#define NSEQ  1024
#define NDIM  64
#define NPAIR 5
#define NPB   40               // pair*8 + batch
#define NDIAG 2047
#define DSTRIDE ((size_t)2048 * 1024)   // padded: diag 2047 is permanent zeros

// tensor order matches d_in: 0=TGT, 1=OTH, 2=X
__constant__ int c_pa[NPAIR] = {2, 0, 0, 1, 1};  // first arg (rows i)
__constant__ int c_pb[NPAIR] = {2, 2, 0, 2, 1};  // second arg (rows j)

__device__ float g_norm[3 * NB * NSEQ * NDIM];            // ~6 MB
__device__ float g_w[NPB * 2048 * 1024];                  // exp(dot-1), diag-major; invalid = 0
__device__ float g_sdtw[NPB];

// ---------------------------------------------------------------------------
// Kernel 1: row-normalize all three tensors. One warp per row.
// ---------------------------------------------------------------------------
__global__ void norm_kernel(const float* __restrict__ TGT,
                            const float* __restrict__ OTH,
                            const float* __restrict__ X) {
    int row  = blockIdx.x * 8 + (threadIdx.x >> 5);   // 0 .. 24575
    int lane = threadIdx.x & 31;
    const float* src = (row < 8192) ? TGT : (row < 16384 ? OTH : X);
    int lrow = row & 8191;
    float2 v = reinterpret_cast<const float2*>(src + (size_t)lrow * NDIM)[lane];
    float s = v.x * v.x + v.y * v.y;
    #pragma unroll
    for (int o = 16; o; o >>= 1) s += __shfl_xor_sync(0xffffffffu, s, o);
    float scale = (s > 1e-16f) ? rsqrtf(s) : 1e8f;
    float2 out = make_float2(v.x * scale, v.y * scale);
    reinterpret_cast<float2*>(g_norm + (size_t)row * NDIM)[lane] = out;
}

// ---------------------------------------------------------------------------
// Kernel 2: w = exp(A_n . B_n^T - 1) per (pair,batch), written DIAGONAL-MAJOR.
// 128x128 tile per CTA, K=64 in chunks of 16, 256 threads, 8x8 micro-tile.
// ---------------------------------------------------------------------------
__global__ void __launch_bounds__(256) cost_kernel() {
    const int pb    = blockIdx.y;           // 0..39
    const int pair  = pb >> 3;
    const int batch = pb & 7;
    const int ti    = blockIdx.x >> 3;
    const int tj    = blockIdx.x & 7;
    const int i0 = ti * 128, j0 = tj * 128;

    const float* Ap = g_norm + ((size_t)(c_pa[pair] * NB + batch)) * NSEQ * NDIM + (size_t)i0 * NDIM;
    const float* Bp = g_norm + ((size_t)(c_pb[pair] * NB + batch)) * NSEQ * NDIM + (size_t)j0 * NDIM;

    __shared__ float sbuf[4608];            // As[16][128] | Bs[16][128] ; reused as Cs[32][136]
    float* As = sbuf;
    float* Bs = sbuf + 2048;

    const int t  = threadIdx.x;
    const int tx = t & 15, ty = t >> 4;

    float acc[8][8];
    #pragma unroll
    for (int u = 0; u < 8; u++)
        #pragma unroll
        for (int v = 0; v < 8; v++) acc[u][v] = 0.f;

    for (int kc = 0; kc < NDIM; kc += 16) {
        __syncthreads();
        #pragma unroll
        for (int q = 0; q < 2; q++) {
            int id = t * 2 + q;             // 0..511
            int r  = id >> 2;               // row within tile
            int kq = id & 3;                // which float4 of the 16-wide K chunk
            float4 va = reinterpret_cast<const float4*>(Ap + r * NDIM + kc)[kq];
            As[(kq * 4 + 0) * 128 + r] = va.x;
            As[(kq * 4 + 1) * 128 + r] = va.y;
            As[(kq * 4 + 2) * 128 + r] = va.z;
            As[(kq * 4 + 3) * 128 + r] = va.w;
            float4 vb = reinterpret_cast<const float4*>(Bp + r * NDIM + kc)[kq];
            Bs[(kq * 4 + 0) * 128 + r] = vb.x;
            Bs[(kq * 4 + 1) * 128 + r] = vb.y;
            Bs[(kq * 4 + 2) * 128 + r] = vb.z;
            Bs[(kq * 4 + 3) * 128 + r] = vb.w;
        }
        __syncthreads();
        #pragma unroll
        for (int kk = 0; kk < 16; kk++) {
            float a[8], b[8];
            *(float4*)(a)     = *(float4*)&As[kk * 128 + ty * 8];
            *(float4*)(a + 4) = *(float4*)&As[kk * 128 + ty * 8 + 4];
            *(float4*)(b)     = *(float4*)&Bs[kk * 128 + tx * 8];
            *(float4*)(b + 4) = *(float4*)&Bs[kk * 128 + tx * 8 + 4];
            #pragma unroll
            for (int u = 0; u < 8; u++)
                #pragma unroll
                for (int v = 0; v < 8; v++) acc[u][v] += a[u] * b[v];
        }
    }

    // epilogue: 4 chunks of 32 rows, diag-major coalesced writes of exp(dot-1)
    float* Cs = sbuf;                       // 32 x 136
    const size_t dbase = (size_t)pb * DSTRIDE;
    const int wid = t >> 5, lane = t & 31;
    for (int c = 0; c < 4; c++) {
        __syncthreads();
        if ((ty >> 2) == c) {
            int ri = (ty & 3) * 8;
            #pragma unroll
            for (int u = 0; u < 8; u++) {
                *(float4*)&Cs[(ri + u) * 136 + tx * 8]     = *(float4*)&acc[u][0];
                *(float4*)&Cs[(ri + u) * 136 + tx * 8 + 4] = *(float4*)&acc[u][4];
            }
        }
        __syncthreads();
        int kb  = i0 + j0 + c * 32;         // global k of local diag 0
        int gi0 = i0 + c * 32;
        for (int kl = wid; kl < 159; kl += 8) {
            int ri = lane;
            int jl = kl - ri;
            if (jl >= 0 && jl < 128 && ri < 32) {
                g_w[dbase + (size_t)(kb + kl) * NSEQ + (gi0 + ri)] =
                    __expf(Cs[ri * 136 + jl] - 1.0f);
            }
        }
    }
}

// ---------------------------------------------------------------------------
// Kernel 3: exp-domain soft-DTW DP. One CTA per (pair,batch), 256 threads,
// 4 rows/thread. E[i,k] = w * (E1[i] + E1[i-1] + E2[i-1]); invalid cells are
// exactly 0 (unwritten zeros in g_w), which propagates INF semantics for free.
// Block-max rescale every 32 steps; L accumulates -log(scale) to recover R.
// ---------------------------------------------------------------------------
__global__ void __launch_bounds__(256, 1) dp_kernel() {
    const int pb   = blockIdx.x;
    const int tid  = threadIdx.x;
    const int lane = tid & 31;
    const int wp   = tid >> 5;

    const float4* base =
        reinterpret_cast<const float4*>(g_w + (size_t)pb * DSTRIDE) + tid;

    __shared__ float bd[2][9];   // bd[parity][wp+1]; column 0 = permanent 0 wall
    __shared__ float wm[8];
    if (tid < 18) ((float*)bd)[tid] = 0.f;
    __syncthreads();

    float E1[4]  = {0.f, 0.f, 0.f, 0.f};   // diag k-1
    float E2s[4] = {0.f, 0.f, 0.f, 0.f};   // diag k-2, shifted by one row
    if (tid == 0) E2s[0] = 1.0f;           // virtual corner exp(-R[-1,-1]) = 1
    float L = 0.f;                          // L = -sum(log m) over rescales

    float4 bufA[8], bufB[8];
    #pragma unroll
    for (int s = 0; s < 8; s++) bufA[s] = base[(size_t)s * 256];

    #define DP_STEP(WV, K)                                                        \
    do {                                                                          \
        float nb = __shfl_up_sync(0xffffffffu, E1[3], 1);                         \
        if (lane == 0) nb = bd[((K) & 1) ^ 1][wp];                                \
        float sh0 = nb, sh1 = E1[0], sh2 = E1[1], sh3 = E1[2];                    \
        float n0 = (WV).x * ((E1[0] + sh0) + E2s[0]);                             \
        float n1 = (WV).y * ((E1[1] + sh1) + E2s[1]);                             \
        float n2 = (WV).z * ((E1[2] + sh2) + E2s[2]);                             \
        float n3 = (WV).w * ((E1[3] + sh3) + E2s[3]);                             \
        E2s[0] = sh0; E2s[1] = sh1; E2s[2] = sh2; E2s[3] = sh3;                   \
        E1[0] = n0; E1[1] = n1; E1[2] = n2; E1[3] = n3;                           \
        if (((K) & 31) == 31) {                                                   \
            float m = fmaxf(fmaxf(fmaxf(n0, n1), fmaxf(n2, n3)),                  \
                            fmaxf(fmaxf(E2s[0], E2s[1]), fmaxf(E2s[2], E2s[3]))); \
            _Pragma("unroll")                                                     \
            for (int o = 16; o; o >>= 1)                                          \
                m = fmaxf(m, __shfl_xor_sync(0xffffffffu, m, o));                 \
            if (lane == 0) wm[wp] = m;                                            \
            __syncthreads();                                                      \
            m = wm[0];                                                            \
            _Pragma("unroll")                                                     \
            for (int q = 1; q < 8; q++) m = fmaxf(m, wm[q]);                      \
            float sc = 1.0f / m;                                                  \
            L -= __logf(m);                                                       \
            E1[0] *= sc; E1[1] *= sc; E1[2] *= sc; E1[3] *= sc;                   \
            E2s[0] *= sc; E2s[1] *= sc; E2s[2] *= sc; E2s[3] *= sc;               \
        }                                                                         \
        if (lane == 31) bd[(K) & 1][wp + 1] = E1[3];                              \
        __syncthreads();                                                          \
    } while (0)

    for (int g = 0; g < 255; g++) {
        #pragma unroll
        for (int s = 0; s < 8; s++)
            bufB[s] = base[(size_t)((g + 1) * 8 + s) * 256];
        const int k0 = g * 8;
        #pragma unroll
        for (int s = 0; s < 8; s++) DP_STEP(bufA[s], k0 + s);
        #pragma unroll
        for (int s = 0; s < 8; s++) bufA[s] = bufB[s];
    }
    // tail: steps 2040..2046 (group 255; its 8th slot is the zero pad diag)
    {
        const int k0 = 255 * 8;
        #pragma unroll
        for (int s = 0; s < 7; s++) DP_STEP(bufA[s], k0 + s);
    }
    #undef DP_STEP

    if (tid == 255) g_sdtw[pb] = L - __logf(E1[3]);   // R[1023][1023]
}

// ---------------------------------------------------------------------------
// Kernel 4: final MSE reduction
// ---------------------------------------------------------------------------
__global__ void final_kernel(const float* __restrict__ labels, float* __restrict__ out) {
    int b = threadIdx.x;
    float v = 0.f;
    if (b < NB) {
        float sXX = g_sdtw[0 * NB + b];
        float sTX = g_sdtw[1 * NB + b];
        float sTT = g_sdtw[2 * NB + b];
        float sOX = g_sdtw[3 * NB + b];
        float sOO = g_sdtw[4 * NB + b];
        float dt = sTX - 0.5f * (sTT + sXX);
        float dq = sOX - 0.5f * (sOO + sXX);
        float e  = dt - dq - labels[0];
        v = e * e;
    }
    #pragma unroll
    for (int o = 16; o; o >>= 1) v += __shfl_xor_sync(0xffffffffu, v, o);
    if (b == 0) out[0] = v * (1.0f / NB);
}

// ---------------------------------------------------------------------------
extern "C" void kernel_launch(void* const* d_in, const int* in_sizes, int n_in,
                              void* d_out, int out_size) {
    const float* TGT    = (const float*)d_in[0];
    const float* OTH    = (const float*)d_in[1];
    const float* X      = (const float*)d_in[2];
    const float* labels = (const float*)d_in[3];
    float* out = (float*)d_out;

    norm_kernel<<<3072, 256>>>(TGT, OTH, X);
    cost_kernel<<<dim3(64, NPB), 256>>>();
    dp_kernel<<<NPB, 256>>>();
    final_kernel<<<1, 32>>>(labels, out);
}

// round 6
// speedup vs baseline: 2.7431x; 1.0394x over previous
#include <cuda_runtime.h>
#include <math.h>

#define NB    8
#define NSEQ  1024
#define NDIM  64
#define NPAIR 5
#define NPB   40               // pair*8 + batch
#define NDIAG 2047
#define DSTRIDE ((size_t)2048 * 1024)   // padded: diag 2047 is permanent zeros

// tensor order matches d_in: 0=TGT, 1=OTH, 2=X
__constant__ int c_pa[NPAIR] = {2, 0, 0, 1, 1};  // first arg (rows i)
__constant__ int c_pb[NPAIR] = {2, 2, 0, 2, 1};  // second arg (rows j)

__device__ float g_norm[3 * NB * NSEQ * NDIM];            // ~6 MB
__device__ float g_w[NPB * 2048 * 1024];                  // exp(dot-1), diag-major; invalid = 0
__device__ float g_sdtw[NPB];

// ---------------------------------------------------------------------------
// Kernel 1: row-normalize all three tensors. One warp per row.
// ---------------------------------------------------------------------------
__global__ void norm_kernel(const float* __restrict__ TGT,
                            const float* __restrict__ OTH,
                            const float* __restrict__ X) {
    int row  = blockIdx.x * 8 + (threadIdx.x >> 5);   // 0 .. 24575
    int lane = threadIdx.x & 31;
    const float* src = (row < 8192) ? TGT : (row < 16384 ? OTH : X);
    int lrow = row & 8191;
    float2 v = reinterpret_cast<const float2*>(src + (size_t)lrow * NDIM)[lane];
    float s = v.x * v.x + v.y * v.y;
    #pragma unroll
    for (int o = 16; o; o >>= 1) s += __shfl_xor_sync(0xffffffffu, s, o);
    float scale = (s > 1e-16f) ? rsqrtf(s) : 1e8f;
    float2 out = make_float2(v.x * scale, v.y * scale);
    reinterpret_cast<float2*>(g_norm + (size_t)row * NDIM)[lane] = out;
}

// ---------------------------------------------------------------------------
// Kernel 2: w = exp(A_n . B_n^T - 1), DIAGONAL-MAJOR output.
// 3xTF32 tensor-core MMA (hi*hi + hi*lo + lo*hi = fp32-accurate dot).
// 128x128 tile/CTA, 8 warps, each warp 16(M)x128(N). K staged 32-wide in fp32;
// hi/lo tf32 split computed in-register at fragment load.
// ---------------------------------------------------------------------------
__device__ __forceinline__ unsigned f2tf32(float x) {
    unsigned r;
    asm("cvt.rna.tf32.f32 %0, %1;" : "=r"(r) : "f"(x));
    return r;
}

#define MMA_TF32(ACC, A0, A1, A2, A3, B0, B1)                                   \
    asm volatile(                                                               \
        "mma.sync.aligned.m16n8k8.row.col.f32.tf32.tf32.f32 "                   \
        "{%0,%1,%2,%3}, {%4,%5,%6,%7}, {%8,%9}, {%0,%1,%2,%3};"                 \
        : "+f"((ACC)[0]), "+f"((ACC)[1]), "+f"((ACC)[2]), "+f"((ACC)[3])        \
        : "r"(A0), "r"(A1), "r"(A2), "r"(A3), "r"(B0), "r"(B1))

__global__ void __launch_bounds__(256) cost_kernel() {
    const int pb    = blockIdx.y;           // 0..39
    const int pair  = pb >> 3;
    const int batch = pb & 7;
    const int ti    = blockIdx.x >> 3;
    const int tj    = blockIdx.x & 7;
    const int i0 = ti * 128, j0t = tj * 128;

    const float* Ap = g_norm + ((size_t)(c_pa[pair] * NB + batch)) * NSEQ * NDIM + (size_t)i0 * NDIM;
    const float* Bp = g_norm + ((size_t)(c_pb[pair] * NB + batch)) * NSEQ * NDIM + (size_t)j0t * NDIM;

    __shared__ float As[128 * 36];          // 18 KB, fp32, 32-wide K chunk, pad 36
    __shared__ float Bs[128 * 36];          // 18 KB

    const int t    = threadIdx.x;
    const int w    = t >> 5;
    const int lane = t & 31;
    const int lq   = lane >> 2;             // fragment row group
    const int lr   = lane & 3;              // fragment k index
    const int m0   = w * 16;

    float acc[16][4];
    #pragma unroll
    for (int j = 0; j < 16; j++)
        #pragma unroll
        for (int c = 0; c < 4; c++) acc[j][c] = 0.f;

    for (int kc0 = 0; kc0 < NDIM; kc0 += 32) {
        __syncthreads();
        #pragma unroll
        for (int p = 0; p < 4; p++) {
            int f4 = t + p * 256;           // 0..1023
            int row = f4 >> 3, q = f4 & 7;
            *reinterpret_cast<float4*>(&As[row * 36 + q * 4]) =
                *reinterpret_cast<const float4*>(Ap + row * NDIM + kc0 + q * 4);
            *reinterpret_cast<float4*>(&Bs[row * 36 + q * 4]) =
                *reinterpret_cast<const float4*>(Bp + row * NDIM + kc0 + q * 4);
        }
        __syncthreads();

        #pragma unroll
        for (int kk = 0; kk < 4; kk++) {
            const int k = kk * 8;
            float af[4];
            af[0] = As[(m0 + lq) * 36 + k + lr];
            af[1] = As[(m0 + lq + 8) * 36 + k + lr];
            af[2] = As[(m0 + lq) * 36 + k + lr + 4];
            af[3] = As[(m0 + lq + 8) * 36 + k + lr + 4];
            unsigned ahi[4], alo[4];
            #pragma unroll
            for (int u = 0; u < 4; u++) {
                ahi[u] = f2tf32(af[u]);
                alo[u] = f2tf32(af[u] - __uint_as_float(ahi[u]));
            }
            #pragma unroll
            for (int j = 0; j < 16; j++) {
                float bf0 = Bs[(j * 8 + lq) * 36 + k + lr];
                float bf1 = Bs[(j * 8 + lq) * 36 + k + lr + 4];
                unsigned bhi0 = f2tf32(bf0);
                unsigned blo0 = f2tf32(bf0 - __uint_as_float(bhi0));
                unsigned bhi1 = f2tf32(bf1);
                unsigned blo1 = f2tf32(bf1 - __uint_as_float(bhi1));
                MMA_TF32(acc[j], ahi[0], ahi[1], ahi[2], ahi[3], bhi0, bhi1);
                MMA_TF32(acc[j], ahi[0], ahi[1], ahi[2], ahi[3], blo0, blo1);
                MMA_TF32(acc[j], alo[0], alo[1], alo[2], alo[3], bhi0, bhi1);
            }
        }
    }

    // epilogue: 4 chunks of 32 rows; stage to SMEM, diag-major exp writes
    float* Cs = As;                         // 32 x 136 = 17.4 KB, fits
    const size_t dbase = (size_t)pb * DSTRIDE;
    for (int c = 0; c < 4; c++) {
        __syncthreads();
        if ((w >> 1) == c) {                // warps 2c, 2c+1 own rows [32c,32c+32)
            int rbase = (w & 1) * 16 + lq;
            #pragma unroll
            for (int j = 0; j < 16; j++) {
                int col = j * 8 + 2 * lr;
                Cs[rbase * 136 + col]           = acc[j][0];
                Cs[rbase * 136 + col + 1]       = acc[j][1];
                Cs[(rbase + 8) * 136 + col]     = acc[j][2];
                Cs[(rbase + 8) * 136 + col + 1] = acc[j][3];
            }
        }
        __syncthreads();
        int kb  = i0 + j0t + c * 32;        // global k of local diag 0
        int gi0 = i0 + c * 32;
        for (int kl = w; kl < 159; kl += 8) {
            int ri = lane;
            int jl = kl - ri;
            if (jl >= 0 && jl < 128 && ri < 32) {
                g_w[dbase + (size_t)(kb + kl) * NSEQ + (gi0 + ri)] =
                    __expf(Cs[ri * 136 + jl] - 1.0f);
            }
        }
    }
}

// ---------------------------------------------------------------------------
// Kernel 3: exp-domain soft-DTW DP. One CTA per (pair,batch), 256 threads,
// 4 rows/thread. E[i,k] = w * (E1[i] + E1[i-1] + E2[i-1]); invalid cells are
// exactly 0 (unwritten zeros in g_w), which propagates INF semantics for free.
// Block-max rescale every 32 steps; L accumulates -log(scale) to recover R.
// ---------------------------------------------------------------------------
__global__ void __launch_bounds__(256, 1) dp_kernel() {
    const int pb   = blockIdx.x;
    const int tid  = threadIdx.x;
    const int lane = tid & 31;
    const int wp   = tid >> 5;

    const float4* base =
        reinterpret_cast<const float4*>(g_w + (size_t)pb * DSTRIDE) + tid;

    __shared__ float bd[2][9];   // bd[parity][wp+1]; column 0 = permanent 0 wall
    __shared__ float wm[8];
    if (tid < 18) ((float*)bd)[tid] = 0.f;
    __syncthreads();

    float E1[4]  = {0.f, 0.f, 0.f, 0.f};   // diag k-1
    float E2s[4] = {0.f, 0.f, 0.f, 0.f};   // diag k-2, shifted by one row
    if (tid == 0) E2s[0] = 1.0f;           // virtual corner exp(-R[-1,-1]) = 1
    float L = 0.f;                          // L = -sum(log m) over rescales

    float4 bufA[8], bufB[8];
    #pragma unroll
    for (int s = 0; s < 8; s++) bufA[s] = base[(size_t)s * 256];

    #define DP_STEP(WV, K)                                                        \
    do {                                                                          \
        float nb = __shfl_up_sync(0xffffffffu, E1[3], 1);                         \
        if (lane == 0) nb = bd[((K) & 1) ^ 1][wp];                                \
        float sh0 = nb, sh1 = E1[0], sh2 = E1[1], sh3 = E1[2];                    \
        float n0 = (WV).x * ((E1[0] + sh0) + E2s[0]);                             \
        float n1 = (WV).y * ((E1[1] + sh1) + E2s[1]);                             \
        float n2 = (WV).z * ((E1[2] + sh2) + E2s[2]);                             \
        float n3 = (WV).w * ((E1[3] + sh3) + E2s[3]);                             \
        E2s[0] = sh0; E2s[1] = sh1; E2s[2] = sh2; E2s[3] = sh3;                   \
        E1[0] = n0; E1[1] = n1; E1[2] = n2; E1[3] = n3;                           \
        if (((K) & 31) == 31) {                                                   \
            float m = fmaxf(fmaxf(fmaxf(n0, n1), fmaxf(n2, n3)),                  \
                            fmaxf(fmaxf(E2s[0], E2s[1]), fmaxf(E2s[2], E2s[3]))); \
            _Pragma("unroll")                                                     \
            for (int o = 16; o; o >>= 1)                                          \
                m = fmaxf(m, __shfl_xor_sync(0xffffffffu, m, o));                 \
            if (lane == 0) wm[wp] = m;                                            \
            __syncthreads();                                                      \
            m = wm[0];                                                            \
            _Pragma("unroll")                                                     \
            for (int q = 1; q < 8; q++) m = fmaxf(m, wm[q]);                      \
            float sc = 1.0f / m;                                                  \
            L -= __logf(m);                                                       \
            E1[0] *= sc; E1[1] *= sc; E1[2] *= sc; E1[3] *= sc;                   \
            E2s[0] *= sc; E2s[1] *= sc; E2s[2] *= sc; E2s[3] *= sc;               \
        }                                                                         \
        if (lane == 31) bd[(K) & 1][wp + 1] = E1[3];                              \
        __syncthreads();                                                          \
    } while (0)

    for (int g = 0; g < 255; g++) {
        #pragma unroll
        for (int s = 0; s < 8; s++)
            bufB[s] = base[(size_t)((g + 1) * 8 + s) * 256];
        const int k0 = g * 8;
        #pragma unroll
        for (int s = 0; s < 8; s++) DP_STEP(bufA[s], k0 + s);
        #pragma unroll
        for (int s = 0; s < 8; s++) bufA[s] = bufB[s];
    }
    // tail: steps 2040..2046 (group 255; its 8th slot is the zero pad diag)
    {
        const int k0 = 255 * 8;
        #pragma unroll
        for (int s = 0; s < 7; s++) DP_STEP(bufA[s], k0 + s);
    }
    #undef DP_STEP

    if (tid == 255) g_sdtw[pb] = L - __logf(E1[3]);   // R[1023][1023]
}

// ---------------------------------------------------------------------------
// Kernel 4: final MSE reduction
// ---------------------------------------------------------------------------
__global__ void final_kernel(const float* __restrict__ labels, float* __restrict__ out) {
    int b = threadIdx.x;
    float v = 0.f;
    if (b < NB) {
        float sXX = g_sdtw[0 * NB + b];
        float sTX = g_sdtw[1 * NB + b];
        float sTT = g_sdtw[2 * NB + b];
        float sOX = g_sdtw[3 * NB + b];
        float sOO = g_sdtw[4 * NB + b];
        float dt = sTX - 0.5f * (sTT + sXX);
        float dq = sOX - 0.5f * (sOO + sXX);
        float e  = dt - dq - labels[0];
        v = e * e;
    }
    #pragma unroll
    for (int o = 16; o; o >>= 1) v += __shfl_xor_sync(0xffffffffu, v, o);
    if (b == 0) out[0] = v * (1.0f / NB);
}

// ---------------------------------------------------------------------------
extern "C" void kernel_launch(void* const* d_in, const int* in_sizes, int n_in,
                              void* d_out, int out_size) {
    const float* TGT    = (const float*)d_in[0];
    const float* OTH    = (const float*)d_in[1];
    const float* X      = (const float*)d_in[2];
    const float* labels = (const float*)d_in[3];
    float* out = (float*)d_out;

    norm_kernel<<<3072, 256>>>(TGT, OTH, X);
    cost_kernel<<<dim3(64, NPB), 256>>>();
    dp_kernel<<<NPB, 256>>>();
    final_kernel<<<1, 32>>>(labels, out);
}

// round 7
// speedup vs baseline: 3.0818x; 1.1235x over previous
#include <cuda_runtime.h>
#include <math.h>

#define NB    8
#define NSEQ  1024
#define NDIM  64
#define NPAIR 5
#define NPB   40               // pair*8 + batch
#define NDIAG 2047
#define DSTRIDE ((size_t)2048 * 1024)   // padded: diag 2047 is permanent zeros

// tensor order matches d_in: 0=TGT, 1=OTH, 2=X
__constant__ int c_pa[NPAIR] = {2, 0, 0, 1, 1};  // first arg (rows i)
__constant__ int c_pb[NPAIR] = {2, 2, 0, 2, 1};  // second arg (rows j)

__device__ float g_hi[3 * NB * NSEQ * NDIM];              // tf32(x)
__device__ float g_lo[3 * NB * NSEQ * NDIM];              // tf32(x - hi)
__device__ float g_w[NPB * 2048 * 1024];                  // exp(dot-1), diag-major; invalid = 0
__device__ float g_sdtw[NPB];

__device__ __forceinline__ float f2tf32f(float x) {
    unsigned r;
    asm("cvt.rna.tf32.f32 %0, %1;" : "=r"(r) : "f"(x));
    return __uint_as_float(r);
}

// ---------------------------------------------------------------------------
// Kernel 1: row-normalize + precompute tf32 hi/lo split. One warp per row.
// ---------------------------------------------------------------------------
__global__ void norm_kernel(const float* __restrict__ TGT,
                            const float* __restrict__ OTH,
                            const float* __restrict__ X) {
    int row  = blockIdx.x * 8 + (threadIdx.x >> 5);   // 0 .. 24575
    int lane = threadIdx.x & 31;
    const float* src = (row < 8192) ? TGT : (row < 16384 ? OTH : X);
    int lrow = row & 8191;
    float2 v = reinterpret_cast<const float2*>(src + (size_t)lrow * NDIM)[lane];
    float s = v.x * v.x + v.y * v.y;
    #pragma unroll
    for (int o = 16; o; o >>= 1) s += __shfl_xor_sync(0xffffffffu, s, o);
    float scale = (s > 1e-16f) ? rsqrtf(s) : 1e8f;
    float nx = v.x * scale, ny = v.y * scale;
    float hx = f2tf32f(nx), hy = f2tf32f(ny);
    float lx = f2tf32f(nx - hx), ly = f2tf32f(ny - hy);
    reinterpret_cast<float2*>(g_hi + (size_t)row * NDIM)[lane] = make_float2(hx, hy);
    reinterpret_cast<float2*>(g_lo + (size_t)row * NDIM)[lane] = make_float2(lx, ly);
}

// ---------------------------------------------------------------------------
// Kernel 2: w = exp(A_n . B_n^T - 1), DIAGONAL-MAJOR output.
// 3xTF32 MMA with PRE-SPLIT hi/lo operands: inner loop = 4 LDS + 3 HMMA, no ALU.
// 128x128 tile/CTA, 8 warps, warp = 16(M)x128(N). K staged in 4x16-wide chunks.
// Symmetric grams (pair where a==b): skip ti>tj tiles, mirror-write from ti<tj.
// ---------------------------------------------------------------------------
#define MMA_TF32(ACC, A0, A1, A2, A3, B0, B1)                                   \
    asm volatile(                                                               \
        "mma.sync.aligned.m16n8k8.row.col.f32.tf32.tf32.f32 "                   \
        "{%0,%1,%2,%3}, {%4,%5,%6,%7}, {%8,%9}, {%0,%1,%2,%3};"                 \
        : "+f"((ACC)[0]), "+f"((ACC)[1]), "+f"((ACC)[2]), "+f"((ACC)[3])        \
        : "r"(A0), "r"(A1), "r"(A2), "r"(A3), "r"(B0), "r"(B1))

#define SPITCH 20   // 16 K-cols + pad 4: lq*20 mod 32 = {0,20,8,28,16,4,24,12} conflict-free

__global__ void __launch_bounds__(256) cost_kernel() {
    const int pb    = blockIdx.y;           // 0..39
    const int pair  = pb >> 3;
    const int batch = pb & 7;
    const int ti    = blockIdx.x >> 3;
    const int tj    = blockIdx.x & 7;

    const bool sym = (c_pa[pair] == c_pb[pair]);
    if (sym && ti > tj) return;             // uniform across CTA
    const bool mirror = sym && (ti < tj);

    const int i0 = ti * 128, j0t = tj * 128;

    const size_t offA = ((size_t)(c_pa[pair] * NB + batch)) * NSEQ * NDIM + (size_t)i0 * NDIM;
    const size_t offB = ((size_t)(c_pb[pair] * NB + batch)) * NSEQ * NDIM + (size_t)j0t * NDIM;
    const float* Aph = g_hi + offA; const float* Apl = g_lo + offA;
    const float* Bph = g_hi + offB; const float* Bpl = g_lo + offB;

    __shared__ float sm[4 * 128 * SPITCH]; // 40 KB; Ah | Al | Bh | Bl
    float* Ah = sm;
    float* Al = sm + 128 * SPITCH;
    float* Bh = sm + 2 * 128 * SPITCH;
    float* Bl = sm + 3 * 128 * SPITCH;

    const int t    = threadIdx.x;
    const int w    = t >> 5;
    const int lane = t & 31;
    const int lq   = lane >> 2;             // fragment row group
    const int lr   = lane & 3;              // fragment k index
    const int m0   = w * 16;

    float acc[16][4];
    #pragma unroll
    for (int j = 0; j < 16; j++)
        #pragma unroll
        for (int c = 0; c < 4; c++) acc[j][c] = 0.f;

    for (int kc0 = 0; kc0 < NDIM; kc0 += 16) {
        __syncthreads();
        #pragma unroll
        for (int p = 0; p < 2; p++) {
            int f4 = t + p * 256;           // 0..511
            int row = f4 >> 2, q = f4 & 3;  // row 0..127, q 0..3
            size_t goff = (size_t)row * NDIM + kc0 + q * 4;
            int    soff = row * SPITCH + q * 4;
            *reinterpret_cast<float4*>(&Ah[soff]) = *reinterpret_cast<const float4*>(Aph + goff);
            *reinterpret_cast<float4*>(&Al[soff]) = *reinterpret_cast<const float4*>(Apl + goff);
            *reinterpret_cast<float4*>(&Bh[soff]) = *reinterpret_cast<const float4*>(Bph + goff);
            *reinterpret_cast<float4*>(&Bl[soff]) = *reinterpret_cast<const float4*>(Bpl + goff);
        }
        __syncthreads();

        #pragma unroll
        for (int kk = 0; kk < 2; kk++) {
            const int k = kk * 8;
            unsigned ahi[4], alo[4];
            ahi[0] = __float_as_uint(Ah[(m0 + lq) * SPITCH + k + lr]);
            ahi[1] = __float_as_uint(Ah[(m0 + lq + 8) * SPITCH + k + lr]);
            ahi[2] = __float_as_uint(Ah[(m0 + lq) * SPITCH + k + lr + 4]);
            ahi[3] = __float_as_uint(Ah[(m0 + lq + 8) * SPITCH + k + lr + 4]);
            alo[0] = __float_as_uint(Al[(m0 + lq) * SPITCH + k + lr]);
            alo[1] = __float_as_uint(Al[(m0 + lq + 8) * SPITCH + k + lr]);
            alo[2] = __float_as_uint(Al[(m0 + lq) * SPITCH + k + lr + 4]);
            alo[3] = __float_as_uint(Al[(m0 + lq + 8) * SPITCH + k + lr + 4]);
            #pragma unroll
            for (int j = 0; j < 16; j++) {
                int bo = (j * 8 + lq) * SPITCH + k + lr;
                unsigned bhi0 = __float_as_uint(Bh[bo]);
                unsigned bhi1 = __float_as_uint(Bh[bo + 4]);
                unsigned blo0 = __float_as_uint(Bl[bo]);
                unsigned blo1 = __float_as_uint(Bl[bo + 4]);
                MMA_TF32(acc[j], ahi[0], ahi[1], ahi[2], ahi[3], bhi0, bhi1);
                MMA_TF32(acc[j], ahi[0], ahi[1], ahi[2], ahi[3], blo0, blo1);
                MMA_TF32(acc[j], alo[0], alo[1], alo[2], alo[3], bhi0, bhi1);
            }
        }
    }

    // epilogue: 4 chunks of 32 rows; stage to SMEM, diag-major exp writes
    float* Cs = sm;                         // 32 x 136 = 4352 floats, fits
    const size_t dbase = (size_t)pb * DSTRIDE;
    for (int c = 0; c < 4; c++) {
        __syncthreads();
        if ((w >> 1) == c) {                // warps 2c, 2c+1 own rows [32c,32c+32)
            int rbase = (w & 1) * 16 + lq;
            #pragma unroll
            for (int j = 0; j < 16; j++) {
                int col = j * 8 + 2 * lr;
                Cs[rbase * 136 + col]           = acc[j][0];
                Cs[rbase * 136 + col + 1]       = acc[j][1];
                Cs[(rbase + 8) * 136 + col]     = acc[j][2];
                Cs[(rbase + 8) * 136 + col + 1] = acc[j][3];
            }
        }
        __syncthreads();
        int kb  = i0 + j0t + c * 32;        // global k of local diag 0
        int gi0 = i0 + c * 32;
        for (int kl = w; kl < 159; kl += 8) {
            int ri = lane;
            int jl = kl - ri;
            if (jl >= 0 && jl < 128) {
                float val = __expf(Cs[ri * 136 + jl] - 1.0f);
                size_t krow = dbase + (size_t)(kb + kl) * NSEQ;
                g_w[krow + (gi0 + ri)] = val;
                if (mirror) g_w[krow + (j0t + jl)] = val;   // transposed cell, same diag
            }
        }
    }
}

// ---------------------------------------------------------------------------
// Kernel 3: exp-domain soft-DTW DP. One CTA per (pair,batch), 256 threads,
// 4 rows/thread. E[i,k] = w * (E1[i] + E1[i-1] + E2[i-1]); invalid cells are
// exactly 0 (unwritten zeros in g_w), which propagates INF semantics for free.
// Block-max rescale every 32 steps; L accumulates -log(scale) to recover R.
// ---------------------------------------------------------------------------
__global__ void __launch_bounds__(256, 1) dp_kernel() {
    const int pb   = blockIdx.x;
    const int tid  = threadIdx.x;
    const int lane = tid & 31;
    const int wp   = tid >> 5;

    const float4* base =
        reinterpret_cast<const float4*>(g_w + (size_t)pb * DSTRIDE) + tid;

    __shared__ float bd[2][9];   // bd[parity][wp+1]; column 0 = permanent 0 wall
    __shared__ float wm[8];
    if (tid < 18) ((float*)bd)[tid] = 0.f;
    __syncthreads();

    float E1[4]  = {0.f, 0.f, 0.f, 0.f};   // diag k-1
    float E2s[4] = {0.f, 0.f, 0.f, 0.f};   // diag k-2, shifted by one row
    if (tid == 0) E2s[0] = 1.0f;           // virtual corner exp(-R[-1,-1]) = 1
    float L = 0.f;                          // L = -sum(log m) over rescales

    float4 bufA[8], bufB[8];
    #pragma unroll
    for (int s = 0; s < 8; s++) bufA[s] = base[(size_t)s * 256];

    #define DP_STEP(WV, K)                                                        \
    do {                                                                          \
        float nb = __shfl_up_sync(0xffffffffu, E1[3], 1);                         \
        if (lane == 0) nb = bd[((K) & 1) ^ 1][wp];                                \
        float sh0 = nb, sh1 = E1[0], sh2 = E1[1], sh3 = E1[2];                    \
        float n0 = (WV).x * ((E1[0] + sh0) + E2s[0]);                             \
        float n1 = (WV).y * ((E1[1] + sh1) + E2s[1]);                             \
        float n2 = (WV).z * ((E1[2] + sh2) + E2s[2]);                             \
        float n3 = (WV).w * ((E1[3] + sh3) + E2s[3]);                             \
        E2s[0] = sh0; E2s[1] = sh1; E2s[2] = sh2; E2s[3] = sh3;                   \
        E1[0] = n0; E1[1] = n1; E1[2] = n2; E1[3] = n3;                           \
        if (((K) & 31) == 31) {                                                   \
            float m = fmaxf(fmaxf(fmaxf(n0, n1), fmaxf(n2, n3)),                  \
                            fmaxf(fmaxf(E2s[0], E2s[1]), fmaxf(E2s[2], E2s[3]))); \
            _Pragma("unroll")                                                     \
            for (int o = 16; o; o >>= 1)                                          \
                m = fmaxf(m, __shfl_xor_sync(0xffffffffu, m, o));                 \
            if (lane == 0) wm[wp] = m;                                            \
            __syncthreads();                                                      \
            m = wm[0];                                                            \
            _Pragma("unroll")                                                     \
            for (int q = 1; q < 8; q++) m = fmaxf(m, wm[q]);                      \
            float sc = 1.0f / m;                                                  \
            L -= __logf(m);                                                       \
            E1[0] *= sc; E1[1] *= sc; E1[2] *= sc; E1[3] *= sc;                   \
            E2s[0] *= sc; E2s[1] *= sc; E2s[2] *= sc; E2s[3] *= sc;               \
        }                                                                         \
        if (lane == 31) bd[(K) & 1][wp + 1] = E1[3];                              \
        __syncthreads();                                                          \
    } while (0)

    for (int g = 0; g < 255; g++) {
        #pragma unroll
        for (int s = 0; s < 8; s++)
            bufB[s] = base[(size_t)((g + 1) * 8 + s) * 256];
        const int k0 = g * 8;
        #pragma unroll
        for (int s = 0; s < 8; s++) DP_STEP(bufA[s], k0 + s);
        #pragma unroll
        for (int s = 0; s < 8; s++) bufA[s] = bufB[s];
    }
    // tail: steps 2040..2046 (group 255; its 8th slot is the zero pad diag)
    {
        const int k0 = 255 * 8;
        #pragma unroll
        for (int s = 0; s < 7; s++) DP_STEP(bufA[s], k0 + s);
    }
    #undef DP_STEP

    if (tid == 255) g_sdtw[pb] = L - __logf(E1[3]);   // R[1023][1023]
}

// ---------------------------------------------------------------------------
// Kernel 4: final MSE reduction
// ---------------------------------------------------------------------------
__global__ void final_kernel(const float* __restrict__ labels, float* __restrict__ out) {
    int b = threadIdx.x;
    float v = 0.f;
    if (b < NB) {
        float sXX = g_sdtw[0 * NB + b];
        float sTX = g_sdtw[1 * NB + b];
        float sTT = g_sdtw[2 * NB + b];
        float sOX = g_sdtw[3 * NB + b];
        float sOO = g_sdtw[4 * NB + b];
        float dt = sTX - 0.5f * (sTT + sXX);
        float dq = sOX - 0.5f * (sOO + sXX);
        float e  = dt - dq - labels[0];
        v = e * e;
    }
    #pragma unroll
    for (int o = 16; o; o >>= 1) v += __shfl_xor_sync(0xffffffffu, v, o);
    if (b == 0) out[0] = v * (1.0f / NB);
}

// ---------------------------------------------------------------------------
extern "C" void kernel_launch(void* const* d_in, const int* in_sizes, int n_in,
                              void* d_out, int out_size) {
    const float* TGT    = (const float*)d_in[0];
    const float* OTH    = (const float*)d_in[1];
    const float* X      = (const float*)d_in[2];
    const float* labels = (const float*)d_in[3];
    float* out = (float*)d_out;

    norm_kernel<<<3072, 256>>>(TGT, OTH, X);
    cost_kernel<<<dim3(64, NPB), 256>>>();
    dp_kernel<<<NPB, 256>>>();
    final_kernel<<<1, 32>>>(labels, out);
}

// round 8
// speedup vs baseline: 3.3029x; 1.0717x over previous
#include <cuda_runtime.h>
#include <cuda_bf16.h>
#include <math.h>

#define NB    8
#define NSEQ  1024
#define NDIM  64
#define NPAIR 5
#define NPB   40               // pair*8 + batch
#define NDIAG 2047
#define DSTRIDE ((size_t)2048 * 1024)   // padded: diag 2047 is permanent zeros

// tensor order matches d_in: 0=TGT, 1=OTH, 2=X
__constant__ int c_pa[NPAIR] = {2, 0, 0, 1, 1};  // first arg (rows i)
__constant__ int c_pb[NPAIR] = {2, 2, 0, 2, 1};  // second arg (rows j)

__device__ __nv_bfloat16 g_hi[3 * NB * NSEQ * NDIM];      // bf16(x)          ~3 MB
__device__ __nv_bfloat16 g_lo[3 * NB * NSEQ * NDIM];      // bf16(x - hi)     ~3 MB
__device__ float g_w[NPB * 2048 * 1024];                  // exp(dot-1), diag-major; invalid = 0
__device__ float g_sdtw[NPB];

// ---------------------------------------------------------------------------
// Kernel 1: row-normalize + bf16 hi/lo split. One warp per row.
// ---------------------------------------------------------------------------
__global__ void norm_kernel(const float* __restrict__ TGT,
                            const float* __restrict__ OTH,
                            const float* __restrict__ X) {
    int row  = blockIdx.x * 8 + (threadIdx.x >> 5);   // 0 .. 24575
    int lane = threadIdx.x & 31;
    const float* src = (row < 8192) ? TGT : (row < 16384 ? OTH : X);
    int lrow = row & 8191;
    float2 v = reinterpret_cast<const float2*>(src + (size_t)lrow * NDIM)[lane];
    float s = v.x * v.x + v.y * v.y;
    #pragma unroll
    for (int o = 16; o; o >>= 1) s += __shfl_xor_sync(0xffffffffu, s, o);
    float scale = (s > 1e-16f) ? rsqrtf(s) : 1e8f;
    float nx = v.x * scale, ny = v.y * scale;
    __nv_bfloat16 hx = __float2bfloat16(nx);
    __nv_bfloat16 hy = __float2bfloat16(ny);
    __nv_bfloat16 lx = __float2bfloat16(nx - __bfloat162float(hx));
    __nv_bfloat16 ly = __float2bfloat16(ny - __bfloat162float(hy));
    __nv_bfloat162 hp; hp.x = hx; hp.y = hy;
    __nv_bfloat162 lp; lp.x = lx; lp.y = ly;
    reinterpret_cast<__nv_bfloat162*>(g_hi + (size_t)row * NDIM)[lane] = hp;
    reinterpret_cast<__nv_bfloat162*>(g_lo + (size_t)row * NDIM)[lane] = lp;
}

// ---------------------------------------------------------------------------
// Kernel 2: w = exp(A_n . B_n^T - 1), DIAGONAL-MAJOR output.
// 3xBF16 MMA (hi*hi + hi*lo + lo*hi): ~17-bit effective mantissa, half the
// MMA and LDS issue count of 3xTF32. 128x128 tile/CTA, 8 warps,
// warp = 16(M)x128(N). K staged in 2x32-half chunks, pitch 40 (conflict-free).
// Symmetric grams: skip ti>tj tiles, mirror-write from ti<tj.
// ---------------------------------------------------------------------------
#define MMA_BF16(ACC, A0, A1, A2, A3, B0, B1)                                   \
    asm volatile(                                                               \
        "mma.sync.aligned.m16n8k16.row.col.f32.bf16.bf16.f32 "                  \
        "{%0,%1,%2,%3}, {%4,%5,%6,%7}, {%8,%9}, {%0,%1,%2,%3};"                 \
        : "+f"((ACC)[0]), "+f"((ACC)[1]), "+f"((ACC)[2]), "+f"((ACC)[3])        \
        : "r"(A0), "r"(A1), "r"(A2), "r"(A3), "r"(B0), "r"(B1))

#define HPITCH 40   // halves per row (32 + 8 pad): word stride 20 -> conflict-free

__global__ void __launch_bounds__(256) cost_kernel() {
    const int pb    = blockIdx.y;           // 0..39
    const int pair  = pb >> 3;
    const int batch = pb & 7;
    const int ti    = blockIdx.x >> 3;
    const int tj    = blockIdx.x & 7;

    const bool sym = (c_pa[pair] == c_pb[pair]);
    if (sym && ti > tj) return;             // uniform across CTA
    const bool mirror = sym && (ti < tj);

    const int i0 = ti * 128, j0t = tj * 128;

    const size_t offA = ((size_t)(c_pa[pair] * NB + batch)) * NSEQ * NDIM + (size_t)i0 * NDIM;
    const size_t offB = ((size_t)(c_pb[pair] * NB + batch)) * NSEQ * NDIM + (size_t)j0t * NDIM;
    const __nv_bfloat16* Aph = g_hi + offA; const __nv_bfloat16* Apl = g_lo + offA;
    const __nv_bfloat16* Bph = g_hi + offB; const __nv_bfloat16* Bpl = g_lo + offB;

    __shared__ __align__(16) __nv_bfloat16 sm[4 * 128 * HPITCH];  // 40 KB
    __nv_bfloat16* Ah = sm;
    __nv_bfloat16* Al = sm + 128 * HPITCH;
    __nv_bfloat16* Bh = sm + 2 * 128 * HPITCH;
    __nv_bfloat16* Bl = sm + 3 * 128 * HPITCH;

    const int t    = threadIdx.x;
    const int w    = t >> 5;
    const int lane = t & 31;
    const int lq   = lane >> 2;             // fragment row group
    const int lr   = lane & 3;              // fragment k index
    const int m0   = w * 16;

    float acc[16][4];
    #pragma unroll
    for (int j = 0; j < 16; j++)
        #pragma unroll
        for (int c = 0; c < 4; c++) acc[j][c] = 0.f;

    for (int kc0 = 0; kc0 < NDIM; kc0 += 32) {
        __syncthreads();
        // stage 128 rows x 32 halves of each of the 4 arrays (uint4 = 8 halves)
        #pragma unroll
        for (int p = 0; p < 2; p++) {
            int f = t + p * 256;            // 0..511
            int row = f >> 2, q = f & 3;
            size_t go = (size_t)row * NDIM + kc0 + q * 8;
            int    so = row * HPITCH + q * 8;
            *reinterpret_cast<uint4*>(&Ah[so]) = *reinterpret_cast<const uint4*>(&Aph[go]);
            *reinterpret_cast<uint4*>(&Al[so]) = *reinterpret_cast<const uint4*>(&Apl[go]);
            *reinterpret_cast<uint4*>(&Bh[so]) = *reinterpret_cast<const uint4*>(&Bph[go]);
            *reinterpret_cast<uint4*>(&Bl[so]) = *reinterpret_cast<const uint4*>(&Bpl[go]);
        }
        __syncthreads();

        #pragma unroll
        for (int kk = 0; kk < 2; kk++) {
            const int k = kk * 16;          // half-index within chunk
            unsigned ahi[4], alo[4];
            int ab = (m0 + lq) * HPITCH + k + 2 * lr;
            int ab8 = (m0 + lq + 8) * HPITCH + k + 2 * lr;
            ahi[0] = *reinterpret_cast<unsigned*>(&Ah[ab]);
            ahi[1] = *reinterpret_cast<unsigned*>(&Ah[ab8]);
            ahi[2] = *reinterpret_cast<unsigned*>(&Ah[ab + 8]);
            ahi[3] = *reinterpret_cast<unsigned*>(&Ah[ab8 + 8]);
            alo[0] = *reinterpret_cast<unsigned*>(&Al[ab]);
            alo[1] = *reinterpret_cast<unsigned*>(&Al[ab8]);
            alo[2] = *reinterpret_cast<unsigned*>(&Al[ab + 8]);
            alo[3] = *reinterpret_cast<unsigned*>(&Al[ab8 + 8]);
            #pragma unroll
            for (int j = 0; j < 16; j++) {
                int bo = (j * 8 + lq) * HPITCH + k + 2 * lr;
                unsigned bhi0 = *reinterpret_cast<unsigned*>(&Bh[bo]);
                unsigned bhi1 = *reinterpret_cast<unsigned*>(&Bh[bo + 8]);
                unsigned blo0 = *reinterpret_cast<unsigned*>(&Bl[bo]);
                unsigned blo1 = *reinterpret_cast<unsigned*>(&Bl[bo + 8]);
                MMA_BF16(acc[j], ahi[0], ahi[1], ahi[2], ahi[3], bhi0, bhi1);
                MMA_BF16(acc[j], ahi[0], ahi[1], ahi[2], ahi[3], blo0, blo1);
                MMA_BF16(acc[j], alo[0], alo[1], alo[2], alo[3], bhi0, bhi1);
            }
        }
    }

    // epilogue: 4 chunks of 32 rows; stage to SMEM, diag-major exp writes
    float* Cs = reinterpret_cast<float*>(sm);   // 32 x 136 floats = 17.4 KB, fits
    const size_t dbase = (size_t)pb * DSTRIDE;
    for (int c = 0; c < 4; c++) {
        __syncthreads();
        if ((w >> 1) == c) {                // warps 2c, 2c+1 own rows [32c,32c+32)
            int rbase = (w & 1) * 16 + lq;
            #pragma unroll
            for (int j = 0; j < 16; j++) {
                int col = j * 8 + 2 * lr;
                Cs[rbase * 136 + col]           = acc[j][0];
                Cs[rbase * 136 + col + 1]       = acc[j][1];
                Cs[(rbase + 8) * 136 + col]     = acc[j][2];
                Cs[(rbase + 8) * 136 + col + 1] = acc[j][3];
            }
        }
        __syncthreads();
        int kb  = i0 + j0t + c * 32;        // global k of local diag 0
        int gi0 = i0 + c * 32;
        for (int kl = w; kl < 159; kl += 8) {
            int ri = lane;
            int jl = kl - ri;
            if (jl >= 0 && jl < 128) {
                float val = __expf(Cs[ri * 136 + jl] - 1.0f);
                size_t krow = dbase + (size_t)(kb + kl) * NSEQ;
                g_w[krow + (gi0 + ri)] = val;
                if (mirror) g_w[krow + (j0t + jl)] = val;   // transposed cell, same diag
            }
        }
    }
}

// ---------------------------------------------------------------------------
// Kernel 3: exp-domain soft-DTW DP. One CTA per (pair,batch), 256 threads,
// 4 rows/thread. E[i,k] = w * (E1[i] + E1[i-1] + E2[i-1]); invalid cells are
// exactly 0 (unwritten zeros in g_w), which propagates INF semantics for free.
// Block-max rescale every 32 steps; L accumulates -log(scale) to recover R.
// ---------------------------------------------------------------------------
__global__ void __launch_bounds__(256, 1) dp_kernel() {
    const int pb   = blockIdx.x;
    const int tid  = threadIdx.x;
    const int lane = tid & 31;
    const int wp   = tid >> 5;

    const float4* base =
        reinterpret_cast<const float4*>(g_w + (size_t)pb * DSTRIDE) + tid;

    __shared__ float bd[2][9];   // bd[parity][wp+1]; column 0 = permanent 0 wall
    __shared__ float wm[8];
    if (tid < 18) ((float*)bd)[tid] = 0.f;
    __syncthreads();

    float E1[4]  = {0.f, 0.f, 0.f, 0.f};   // diag k-1
    float E2s[4] = {0.f, 0.f, 0.f, 0.f};   // diag k-2, shifted by one row
    if (tid == 0) E2s[0] = 1.0f;           // virtual corner exp(-R[-1,-1]) = 1
    float L = 0.f;                          // L = -sum(log m) over rescales

    float4 bufA[8], bufB[8];
    #pragma unroll
    for (int s = 0; s < 8; s++) bufA[s] = base[(size_t)s * 256];

    #define DP_STEP(WV, K)                                                        \
    do {                                                                          \
        float nb = __shfl_up_sync(0xffffffffu, E1[3], 1);                         \
        if (lane == 0) nb = bd[((K) & 1) ^ 1][wp];                                \
        float sh0 = nb, sh1 = E1[0], sh2 = E1[1], sh3 = E1[2];                    \
        float n0 = (WV).x * ((E1[0] + sh0) + E2s[0]);                             \
        float n1 = (WV).y * ((E1[1] + sh1) + E2s[1]);                             \
        float n2 = (WV).z * ((E1[2] + sh2) + E2s[2]);                             \
        float n3 = (WV).w * ((E1[3] + sh3) + E2s[3]);                             \
        E2s[0] = sh0; E2s[1] = sh1; E2s[2] = sh2; E2s[3] = sh3;                   \
        E1[0] = n0; E1[1] = n1; E1[2] = n2; E1[3] = n3;                           \
        if (((K) & 31) == 31) {                                                   \
            float m = fmaxf(fmaxf(fmaxf(n0, n1), fmaxf(n2, n3)),                  \
                            fmaxf(fmaxf(E2s[0], E2s[1]), fmaxf(E2s[2], E2s[3]))); \
            _Pragma("unroll")                                                     \
            for (int o = 16; o; o >>= 1)                                          \
                m = fmaxf(m, __shfl_xor_sync(0xffffffffu, m, o));                 \
            if (lane == 0) wm[wp] = m;                                            \
            __syncthreads();                                                      \
            m = wm[0];                                                            \
            _Pragma("unroll")                                                     \
            for (int q = 1; q < 8; q++) m = fmaxf(m, wm[q]);                      \
            float sc = 1.0f / m;                                                  \
            L -= __logf(m);                                                       \
            E1[0] *= sc; E1[1] *= sc; E1[2] *= sc; E1[3] *= sc;                   \
            E2s[0] *= sc; E2s[1] *= sc; E2s[2] *= sc; E2s[3] *= sc;               \
        }                                                                         \
        if (lane == 31) bd[(K) & 1][wp + 1] = E1[3];                              \
        __syncthreads();                                                          \
    } while (0)

    for (int g = 0; g < 255; g++) {
        #pragma unroll
        for (int s = 0; s < 8; s++)
            bufB[s] = base[(size_t)((g + 1) * 8 + s) * 256];
        const int k0 = g * 8;
        #pragma unroll
        for (int s = 0; s < 8; s++) DP_STEP(bufA[s], k0 + s);
        #pragma unroll
        for (int s = 0; s < 8; s++) bufA[s] = bufB[s];
    }
    // tail: steps 2040..2046 (group 255; its 8th slot is the zero pad diag)
    {
        const int k0 = 255 * 8;
        #pragma unroll
        for (int s = 0; s < 7; s++) DP_STEP(bufA[s], k0 + s);
    }
    #undef DP_STEP

    if (tid == 255) g_sdtw[pb] = L - __logf(E1[3]);   // R[1023][1023]
}

// ---------------------------------------------------------------------------
// Kernel 4: final MSE reduction
// ---------------------------------------------------------------------------
__global__ void final_kernel(const float* __restrict__ labels, float* __restrict__ out) {
    int b = threadIdx.x;
    float v = 0.f;
    if (b < NB) {
        float sXX = g_sdtw[0 * NB + b];
        float sTX = g_sdtw[1 * NB + b];
        float sTT = g_sdtw[2 * NB + b];
        float sOX = g_sdtw[3 * NB + b];
        float sOO = g_sdtw[4 * NB + b];
        float dt = sTX - 0.5f * (sTT + sXX);
        float dq = sOX - 0.5f * (sOO + sXX);
        float e  = dt - dq - labels[0];
        v = e * e;
    }
    #pragma unroll
    for (int o = 16; o; o >>= 1) v += __shfl_xor_sync(0xffffffffu, v, o);
    if (b == 0) out[0] = v * (1.0f / NB);
}

// ---------------------------------------------------------------------------
extern "C" void kernel_launch(void* const* d_in, const int* in_sizes, int n_in,
                              void* d_out, int out_size) {
    const float* TGT    = (const float*)d_in[0];
    const float* OTH    = (const float*)d_in[1];
    const float* X      = (const float*)d_in[2];
    const float* labels = (const float*)d_in[3];
    float* out = (float*)d_out;

    norm_kernel<<<3072, 256>>>(TGT, OTH, X);
    cost_kernel<<<dim3(64, NPB), 256>>>();
    dp_kernel<<<NPB, 256>>>();
    final_kernel<<<1, 32>>>(labels, out);
}

// round 9
// speedup vs baseline: 4.3567x; 1.3191x over previous
#include <cuda_runtime.h>
#include <cuda_bf16.h>
#include <math.h>

#define NB    8
#define NSEQ  1024
#define NDIM  64
#define NPAIR 5
#define NPB   40               // pair*8 + batch
#define NDIAG 2047
#define NTILES 1888            // 16 pbs * 64 tiles + 24 sym pbs * 36 tiles
#define DSTRIDE ((size_t)2048 * 1024)   // padded: diag 2047 is permanent zeros

// tensor order matches d_in: 0=TGT, 1=OTH, 2=X
__constant__ int c_pa[NPAIR] = {2, 0, 0, 1, 1};  // first arg (rows i)
__constant__ int c_pb[NPAIR] = {2, 2, 0, 2, 1};  // second arg (rows j)

__device__ __nv_bfloat16 g_hi[3 * NB * NSEQ * NDIM];      // bf16(x)
__device__ __nv_bfloat16 g_lo[3 * NB * NSEQ * NDIM];      // bf16(x - hi)
__device__ float g_w[NPB * 2048 * 1024];                  // exp(dot-1), diag-major; invalid = 0
__device__ float g_sdtw[NPB];
__device__ int   g_ticket;                                // producer work queue
__device__ int   g_done[NPB * 16];                        // per-(pb, wave) tile completions

// per-wave tile counts
__device__ __forceinline__ int cnt_ns(int s)  { return 8 - abs(s - 7); }
__device__ __forceinline__ int cnt_sym(int s) { return (s >> 1) - max(0, s - 7) + 1; }

__device__ __forceinline__ int ld_acq(const int* p) {
    int v;
    asm volatile("ld.acquire.gpu.b32 %0, [%1];" : "=r"(v) : "l"(p));
    return v;
}

// ---------------------------------------------------------------------------
// Kernel 1: row-normalize + bf16 hi/lo split. One warp per row.
// Block 0 also resets the producer/consumer bookkeeping for this replay.
// ---------------------------------------------------------------------------
__global__ void norm_kernel(const float* __restrict__ TGT,
                            const float* __restrict__ OTH,
                            const float* __restrict__ X) {
    if (blockIdx.x == 0) {
        if (threadIdx.x == 0) g_ticket = 0;
        for (int i = threadIdx.x; i < NPB * 16; i += 256) g_done[i] = 0;
    }
    int row  = blockIdx.x * 8 + (threadIdx.x >> 5);   // 0 .. 24575
    int lane = threadIdx.x & 31;
    const float* src = (row < 8192) ? TGT : (row < 16384 ? OTH : X);
    int lrow = row & 8191;
    float2 v = reinterpret_cast<const float2*>(src + (size_t)lrow * NDIM)[lane];
    float s = v.x * v.x + v.y * v.y;
    #pragma unroll
    for (int o = 16; o; o >>= 1) s += __shfl_xor_sync(0xffffffffu, s, o);
    float scale = (s > 1e-16f) ? rsqrtf(s) : 1e8f;
    float nx = v.x * scale, ny = v.y * scale;
    __nv_bfloat16 hx = __float2bfloat16(nx);
    __nv_bfloat16 hy = __float2bfloat16(ny);
    __nv_bfloat16 lx = __float2bfloat16(nx - __bfloat162float(hx));
    __nv_bfloat16 ly = __float2bfloat16(ny - __bfloat162float(hy));
    __nv_bfloat162 hp; hp.x = hx; hp.y = hy;
    __nv_bfloat162 lp; lp.x = lx; lp.y = ly;
    reinterpret_cast<__nv_bfloat162*>(g_hi + (size_t)row * NDIM)[lane] = hp;
    reinterpret_cast<__nv_bfloat162*>(g_lo + (size_t)row * NDIM)[lane] = lp;
}

// ---------------------------------------------------------------------------
// Kernel 2 (FUSED): persistent producer/consumer.
//  CTAs 0..39   : exp-domain soft-DTW DP for pb = blockIdx.x, gated per
//                 128-diag wave on g_done counters (acquire spin).
//  CTAs 40..255 : GEMM producers. Global atomic ticket over NTILES tiles,
//                 ordered by wave s = ti+tj so low diagonals complete first.
//                 3xBF16 MMA, diag-major exp writes, mirror for symmetric.
// __launch_bounds__(256,2): 2 CTAs/SM guaranteed -> all 256 CTAs resident
// (148 SMs * 2 = 296 slots) -> consumers can never starve producers.
// ---------------------------------------------------------------------------
#define MMA_BF16(ACC, A0, A1, A2, A3, B0, B1)                                   \
    asm volatile(                                                               \
        "mma.sync.aligned.m16n8k16.row.col.f32.bf16.bf16.f32 "                  \
        "{%0,%1,%2,%3}, {%4,%5,%6,%7}, {%8,%9}, {%0,%1,%2,%3};"                 \
        : "+f"((ACC)[0]), "+f"((ACC)[1]), "+f"((ACC)[2]), "+f"((ACC)[3])        \
        : "r"(A0), "r"(A1), "r"(A2), "r"(A3), "r"(B0), "r"(B1))

#define HPITCH 40   // halves per row (32 + 8 pad): word stride 20 -> conflict-free

__global__ void __launch_bounds__(256, 2) fused_kernel() {
    __shared__ __align__(16) __nv_bfloat16 smbuf[4 * 128 * HPITCH];  // 40 KB (producer)
    __shared__ float bd[2][9];      // DP boundary ring
    __shared__ float wm[8];         // DP rescale reduction
    __shared__ int   sticket;       // producer ticket broadcast

    if (blockIdx.x < NPB) {
        // =================== CONSUMER: soft-DTW DP ===================
        const int pb   = blockIdx.x;
        const int pair = pb >> 3;
        const bool symp = (c_pa[pair] == c_pb[pair]);
        const int tid  = threadIdx.x;
        const int lane = tid & 31;
        const int wp   = tid >> 5;

        const float4* base =
            reinterpret_cast<const float4*>(g_w + (size_t)pb * DSTRIDE) + tid;

        if (tid < 18) ((float*)bd)[tid] = 0.f;
        __syncthreads();

        float E1[4]  = {0.f, 0.f, 0.f, 0.f};
        float E2s[4] = {0.f, 0.f, 0.f, 0.f};
        if (tid == 0) E2s[0] = 1.0f;
        float L = 0.f;

        int s_checked = -1;   // meaningful in thread 0 only
        // wait for wave 0, then initial prefetch of group 0
        if (tid == 0) {
            int need = symp ? cnt_sym(0) : cnt_ns(0);
            while (ld_acq(&g_done[pb * 16]) < need) __nanosleep(128);
            s_checked = 0;
        }
        __syncthreads();

        float4 bufA[8], bufB[8];
        #pragma unroll
        for (int s = 0; s < 8; s++) bufA[s] = base[(size_t)s * 256];

        #define DP_STEP(WV, K)                                                        \
        do {                                                                          \
            float nb = __shfl_up_sync(0xffffffffu, E1[3], 1);                         \
            if (lane == 0) nb = bd[((K) & 1) ^ 1][wp];                                \
            float sh0 = nb, sh1 = E1[0], sh2 = E1[1], sh3 = E1[2];                    \
            float n0 = (WV).x * ((E1[0] + sh0) + E2s[0]);                             \
            float n1 = (WV).y * ((E1[1] + sh1) + E2s[1]);                             \
            float n2 = (WV).z * ((E1[2] + sh2) + E2s[2]);                             \
            float n3 = (WV).w * ((E1[3] + sh3) + E2s[3]);                             \
            E2s[0] = sh0; E2s[1] = sh1; E2s[2] = sh2; E2s[3] = sh3;                   \
            E1[0] = n0; E1[1] = n1; E1[2] = n2; E1[3] = n3;                           \
            if (((K) & 31) == 31) {                                                   \
                float m = fmaxf(fmaxf(fmaxf(n0, n1), fmaxf(n2, n3)),                  \
                                fmaxf(fmaxf(E2s[0], E2s[1]), fmaxf(E2s[2], E2s[3]))); \
                _Pragma("unroll")                                                     \
                for (int o = 16; o; o >>= 1)                                          \
                    m = fmaxf(m, __shfl_xor_sync(0xffffffffu, m, o));                 \
                if (lane == 0) wm[wp] = m;                                            \
                __syncthreads();                                                      \
                m = wm[0];                                                            \
                _Pragma("unroll")                                                     \
                for (int q = 1; q < 8; q++) m = fmaxf(m, wm[q]);                      \
                float sc = 1.0f / m;                                                  \
                L -= __logf(m);                                                       \
                E1[0] *= sc; E1[1] *= sc; E1[2] *= sc; E1[3] *= sc;                   \
                E2s[0] *= sc; E2s[1] *= sc; E2s[2] *= sc; E2s[3] *= sc;               \
            }                                                                         \
            if (lane == 31) bd[(K) & 1][wp + 1] = E1[3];                              \
            __syncthreads();                                                          \
        } while (0)

        for (int g = 0; g < 255; g++) {
            // gate the prefetch of group g+1 (diags 8g+8 .. 8g+15)
            int s_need = min(14, (8 * g + 15) >> 7);
            if (tid == 0) {
                while (s_checked < s_need) {
                    int nw = s_checked + 1;
                    int need = symp ? cnt_sym(nw) : cnt_ns(nw);
                    if (ld_acq(&g_done[pb * 16 + nw]) >= need) s_checked = nw;
                    else __nanosleep(128);
                }
            }
            __syncthreads();
            #pragma unroll
            for (int s = 0; s < 8; s++)
                bufB[s] = base[(size_t)((g + 1) * 8 + s) * 256];
            const int k0 = g * 8;
            #pragma unroll
            for (int s = 0; s < 8; s++) DP_STEP(bufA[s], k0 + s);
            #pragma unroll
            for (int s = 0; s < 8; s++) bufA[s] = bufB[s];
        }
        {   // tail: steps 2040..2046
            const int k0 = 255 * 8;
            #pragma unroll
            for (int s = 0; s < 7; s++) DP_STEP(bufA[s], k0 + s);
        }
        #undef DP_STEP

        if (tid == NSEQ / 4 - 1) g_sdtw[pb] = L - __logf(E1[3]);
        return;
    }

    // =================== PRODUCER: cost tiles ===================
    __nv_bfloat16* Ah = smbuf;
    __nv_bfloat16* Al = smbuf + 128 * HPITCH;
    __nv_bfloat16* Bh = smbuf + 2 * 128 * HPITCH;
    __nv_bfloat16* Bl = smbuf + 3 * 128 * HPITCH;

    const int t    = threadIdx.x;
    const int w    = t >> 5;
    const int lane = t & 31;
    const int lq   = lane >> 2;
    const int lr   = lane & 3;
    const int m0   = w * 16;

    for (;;) {
        if (t == 0) sticket = atomicAdd(&g_ticket, 1);
        __syncthreads();
        const int ticket = sticket;
        if (ticket >= NTILES) return;

        // decode ticket -> (s, pb, ti, tj); tiles ordered by wave s
        int s = 0, acc0 = 0;
        for (;; s++) {
            int wsz = 24 * cnt_sym(s) + 16 * cnt_ns(s);
            if (ticket < acc0 + wsz) break;
            acc0 += wsz;
        }
        int r  = ticket - acc0;
        int cs = cnt_sym(s), cn = cnt_ns(s), lo = max(0, s - 7);
        int pb, ti;
        if (r < 24 * cs) {
            int q = r / cs; ti = lo + (r % cs);
            pb = ((q >> 3) * 2) * 8 + (q & 7);          // pairs 0,2,4 (symmetric)
        } else {
            r -= 24 * cs;
            int q = r / cn; ti = lo + (r % cn);
            pb = ((q >> 3) * 2 + 1) * 8 + (q & 7);      // pairs 1,3
        }
        const int tj = s - ti;
        const int pair  = pb >> 3;
        const int batch = pb & 7;
        const bool mirror = (c_pa[pair] == c_pb[pair]) && (ti < tj);
        const int i0 = ti * 128, j0t = tj * 128;

        const size_t offA = ((size_t)(c_pa[pair] * NB + batch)) * NSEQ * NDIM + (size_t)i0 * NDIM;
        const size_t offB = ((size_t)(c_pb[pair] * NB + batch)) * NSEQ * NDIM + (size_t)j0t * NDIM;
        const __nv_bfloat16* Aph = g_hi + offA; const __nv_bfloat16* Apl = g_lo + offA;
        const __nv_bfloat16* Bph = g_hi + offB; const __nv_bfloat16* Bpl = g_lo + offB;

        float acc[16][4];
        #pragma unroll
        for (int j = 0; j < 16; j++)
            #pragma unroll
            for (int c = 0; c < 4; c++) acc[j][c] = 0.f;

        for (int kc0 = 0; kc0 < NDIM; kc0 += 32) {
            __syncthreads();
            #pragma unroll
            for (int p = 0; p < 2; p++) {
                int f = t + p * 256;
                int row = f >> 2, q = f & 3;
                size_t go = (size_t)row * NDIM + kc0 + q * 8;
                int    so = row * HPITCH + q * 8;
                *reinterpret_cast<uint4*>(&Ah[so]) = *reinterpret_cast<const uint4*>(&Aph[go]);
                *reinterpret_cast<uint4*>(&Al[so]) = *reinterpret_cast<const uint4*>(&Apl[go]);
                *reinterpret_cast<uint4*>(&Bh[so]) = *reinterpret_cast<const uint4*>(&Bph[go]);
                *reinterpret_cast<uint4*>(&Bl[so]) = *reinterpret_cast<const uint4*>(&Bpl[go]);
            }
            __syncthreads();

            #pragma unroll
            for (int kk = 0; kk < 2; kk++) {
                const int k = kk * 16;
                unsigned ahi[4], alo[4];
                int ab  = (m0 + lq) * HPITCH + k + 2 * lr;
                int ab8 = (m0 + lq + 8) * HPITCH + k + 2 * lr;
                ahi[0] = *reinterpret_cast<unsigned*>(&Ah[ab]);
                ahi[1] = *reinterpret_cast<unsigned*>(&Ah[ab8]);
                ahi[2] = *reinterpret_cast<unsigned*>(&Ah[ab + 8]);
                ahi[3] = *reinterpret_cast<unsigned*>(&Ah[ab8 + 8]);
                alo[0] = *reinterpret_cast<unsigned*>(&Al[ab]);
                alo[1] = *reinterpret_cast<unsigned*>(&Al[ab8]);
                alo[2] = *reinterpret_cast<unsigned*>(&Al[ab + 8]);
                alo[3] = *reinterpret_cast<unsigned*>(&Al[ab8 + 8]);
                #pragma unroll
                for (int j = 0; j < 16; j++) {
                    int bo = (j * 8 + lq) * HPITCH + k + 2 * lr;
                    unsigned bhi0 = *reinterpret_cast<unsigned*>(&Bh[bo]);
                    unsigned bhi1 = *reinterpret_cast<unsigned*>(&Bh[bo + 8]);
                    unsigned blo0 = *reinterpret_cast<unsigned*>(&Bl[bo]);
                    unsigned blo1 = *reinterpret_cast<unsigned*>(&Bl[bo + 8]);
                    MMA_BF16(acc[j], ahi[0], ahi[1], ahi[2], ahi[3], bhi0, bhi1);
                    MMA_BF16(acc[j], ahi[0], ahi[1], ahi[2], ahi[3], blo0, blo1);
                    MMA_BF16(acc[j], alo[0], alo[1], alo[2], alo[3], bhi0, bhi1);
                }
            }
        }

        // epilogue: 4 chunks of 32 rows -> SMEM -> diag-major exp writes
        float* Cs = reinterpret_cast<float*>(smbuf);
        const size_t dbase = (size_t)pb * DSTRIDE;
        for (int c = 0; c < 4; c++) {
            __syncthreads();
            if ((w >> 1) == c) {
                int rbase = (w & 1) * 16 + lq;
                #pragma unroll
                for (int j = 0; j < 16; j++) {
                    int col = j * 8 + 2 * lr;
                    Cs[rbase * 136 + col]           = acc[j][0];
                    Cs[rbase * 136 + col + 1]       = acc[j][1];
                    Cs[(rbase + 8) * 136 + col]     = acc[j][2];
                    Cs[(rbase + 8) * 136 + col + 1] = acc[j][3];
                }
            }
            __syncthreads();
            int kb  = i0 + j0t + c * 32;
            int gi0 = i0 + c * 32;
            for (int kl = w; kl < 159; kl += 8) {
                int ri = lane;
                int jl = kl - ri;
                if (jl >= 0 && jl < 128) {
                    float val = __expf(Cs[ri * 136 + jl] - 1.0f);
                    size_t krow = dbase + (size_t)(kb + kl) * NSEQ;
                    g_w[krow + (gi0 + ri)] = val;
                    if (mirror) g_w[krow + (j0t + jl)] = val;
                }
            }
        }
        __syncthreads();
        if (t == 0) {
            __threadfence();                          // release tile writes
            atomicAdd(&g_done[pb * 16 + s], 1);
        }
    }
}

// ---------------------------------------------------------------------------
// Kernel 3: final MSE reduction
// ---------------------------------------------------------------------------
__global__ void final_kernel(const float* __restrict__ labels, float* __restrict__ out) {
    int b = threadIdx.x;
    float v = 0.f;
    if (b < NB) {
        float sXX = g_sdtw[0 * NB + b];
        float sTX = g_sdtw[1 * NB + b];
        float sTT = g_sdtw[2 * NB + b];
        float sOX = g_sdtw[3 * NB + b];
        float sOO = g_sdtw[4 * NB + b];
        float dt = sTX - 0.5f * (sTT + sXX);
        float dq = sOX - 0.5f * (sOO + sXX);
        float e  = dt - dq - labels[0];
        v = e * e;
    }
    #pragma unroll
    for (int o = 16; o; o >>= 1) v += __shfl_xor_sync(0xffffffffu, v, o);
    if (b == 0) out[0] = v * (1.0f / NB);
}

// ---------------------------------------------------------------------------
extern "C" void kernel_launch(void* const* d_in, const int* in_sizes, int n_in,
                              void* d_out, int out_size) {
    const float* TGT    = (const float*)d_in[0];
    const float* OTH    = (const float*)d_in[1];
    const float* X      = (const float*)d_in[2];
    const float* labels = (const float*)d_in[3];
    float* out = (float*)d_out;

    norm_kernel<<<3072, 256>>>(TGT, OTH, X);
    fused_kernel<<<256, 256>>>();
    final_kernel<<<1, 32>>>(labels, out);
}